// round 1
// baseline (speedup 1.0000x reference)
#include <cuda_runtime.h>
#include <math.h>

#define Bb 2
#define Tt 2048
#define Cc 1024
#define Hh 16
#define Dd 64
#define BT (Bb*Tt)      // 4096
#define C3 (3*Cc)       // 3072

// Scratch (allocation-free rule: __device__ globals)
__device__ float g_qkv[(size_t)BT * C3];   // [B,T,3C]
__device__ float g_att[(size_t)BT * Cc];   // attn_v in [B,T,C]

// ---------------------------------------------------------------------------
// Generic tiled fp32 GEMM: out[M,N] = A[M,K] @ W[K,N] + bias[N]
// BM=BN=64, BK=16, 256 threads, 4x4 register tile per thread.
// M,N,K all divisible by tile sizes for this problem (4096/3072/1024).
// ---------------------------------------------------------------------------
__global__ __launch_bounds__(256) void gemm_bias_kernel(
    const float* __restrict__ A, const float* __restrict__ W,
    const float* __restrict__ bias, float* __restrict__ out,
    int M, int N, int K)
{
    const int BM = 64, BN = 64, BK = 16, TM = 4, TN = 4;
    __shared__ float As[BK][BM];
    __shared__ float Bs[BK][BN];

    int tid  = threadIdx.x;
    int tcol = tid % (BN / TN);   // 0..15
    int trow = tid / (BN / TN);   // 0..15
    int row0 = blockIdx.y * BM;
    int col0 = blockIdx.x * BN;

    float acc[TM][TN];
#pragma unroll
    for (int i = 0; i < TM; i++)
#pragma unroll
        for (int j = 0; j < TN; j++) acc[i][j] = 0.f;

    for (int k0 = 0; k0 < K; k0 += BK) {
        // load A tile (transposed into As[k][m])
#pragma unroll
        for (int i = tid; i < BM * BK; i += 256) {
            int r = i / BK, c = i % BK;
            As[c][r] = A[(size_t)(row0 + r) * K + k0 + c];
        }
        // load W tile
#pragma unroll
        for (int i = tid; i < BK * BN; i += 256) {
            int r = i / BN, c = i % BN;
            Bs[r][c] = W[(size_t)(k0 + r) * N + col0 + c];
        }
        __syncthreads();

#pragma unroll
        for (int kk = 0; kk < BK; kk++) {
            float a[TM], b[TN];
#pragma unroll
            for (int i = 0; i < TM; i++) a[i] = As[kk][trow * TM + i];
#pragma unroll
            for (int j = 0; j < TN; j++) b[j] = Bs[kk][tcol * TN + j];
#pragma unroll
            for (int i = 0; i < TM; i++)
#pragma unroll
                for (int j = 0; j < TN; j++) acc[i][j] += a[i] * b[j];
        }
        __syncthreads();
    }

#pragma unroll
    for (int i = 0; i < TM; i++) {
        int r = row0 + trow * TM + i;
#pragma unroll
        for (int j = 0; j < TN; j++) {
            int c = col0 + tcol * TN + j;
            out[(size_t)r * N + c] = acc[i][j] + bias[c];
        }
    }
}

// ---------------------------------------------------------------------------
// Causal attention: one warp per query row. Two passes over keys:
//   pass 1: online (max, sumexp) statistics
//   pass 2: recompute scores, write normalized attn_w row, accumulate P @ V
// qkv layout: [B,T,3C], head h slice at column h*64 (q), C+h*64 (k), 2C+h*64 (v)
// attn_w layout: [B,H,T,T]; att_out layout: [B,T,C]
// ---------------------------------------------------------------------------
__global__ __launch_bounds__(128) void attn_kernel(
    const float* __restrict__ qkv,
    float* __restrict__ attn_w,      // may be null
    float* __restrict__ att_out,
    int write_attn)
{
    const int warp = threadIdx.x >> 5;
    const int lane = threadIdx.x & 31;
    const int qrow = blockIdx.x * 4 + warp;
    const int h = blockIdx.y;
    const int b = blockIdx.z;
    const float scale = 0.125f;   // 1/sqrt(64)

    const float* qp    = qkv + ((size_t)(b * Tt + qrow)) * C3 + h * Dd;
    const float* Kbase = qkv + (size_t)b * Tt * C3 + Cc     + h * Dd;
    const float* Vbase = qkv + (size_t)b * Tt * C3 + 2 * Cc + h * Dd;

    __shared__ float qs[4][Dd];
    __shared__ float ps[4][32];

    for (int d = lane; d < Dd; d += 32) qs[warp][d] = qp[d];
    __syncwarp();
    const float4* qs4 = (const float4*)qs[warp];

    // ---- pass 1: online max / sumexp ----
    float m = -1e30f, l = 0.f;
    for (int j0 = 0; j0 <= qrow; j0 += 32) {
        int j = j0 + lane;
        float s = -1e30f;
        if (j <= qrow) {
            const float4* kp4 = (const float4*)(Kbase + (size_t)j * C3);
            float acc = 0.f;
#pragma unroll
            for (int d = 0; d < Dd / 4; d++) {
                float4 kv = kp4[d];
                float4 qv = qs4[d];
                acc += qv.x * kv.x + qv.y * kv.y + qv.z * kv.z + qv.w * kv.w;
            }
            s = acc * scale;
        }
        float mn = fmaxf(m, s);
        float add = (j <= qrow) ? __expf(s - mn) : 0.f;
        l = l * __expf(m - mn) + add;
        m = mn;
    }
    // warp-reduce (m, l)
#pragma unroll
    for (int off = 16; off; off >>= 1) {
        float m2 = __shfl_xor_sync(0xffffffffu, m, off);
        float l2 = __shfl_xor_sync(0xffffffffu, l, off);
        float mn = fmaxf(m, m2);
        l = l * __expf(m - mn) + l2 * __expf(m2 - mn);
        m = mn;
    }
    float inv_l = 1.f / l;

    // ---- pass 2: write attn row + accumulate P@V ----
    float o0 = 0.f, o1 = 0.f;     // output dims lane, lane+32
    size_t arow = 0;
    if (write_attn) arow = (((size_t)(b * Hh + h)) * Tt + qrow) * (size_t)Tt;

    for (int j0 = 0; j0 < Tt; j0 += 32) {
        int j = j0 + lane;
        float p = 0.f;
        if (j0 <= qrow) {
            if (j <= qrow) {
                const float4* kp4 = (const float4*)(Kbase + (size_t)j * C3);
                float acc = 0.f;
#pragma unroll
                for (int d = 0; d < Dd / 4; d++) {
                    float4 kv = kp4[d];
                    float4 qv = qs4[d];
                    acc += qv.x * kv.x + qv.y * kv.y + qv.z * kv.z + qv.w * kv.w;
                }
                p = __expf(acc * scale - m) * inv_l;
            }
            ps[warp][lane] = p;
            __syncwarp();
            int jmax = min(32, qrow - j0 + 1);
            for (int jj = 0; jj < jmax; jj++) {
                float pj = ps[warp][jj];
                const float* vp = Vbase + (size_t)(j0 + jj) * C3;
                o0 += pj * vp[lane];
                o1 += pj * vp[lane + 32];
            }
            __syncwarp();
        }
        if (write_attn) attn_w[arow + j] = p;
    }

    float* op = att_out + ((size_t)(b * Tt + qrow)) * Cc + h * Dd;
    op[lane] = o0;
    op[lane + 32] = o1;
}

// ---------------------------------------------------------------------------
extern "C" void kernel_launch(void* const* d_in, const int* in_sizes, int n_in,
                              void* d_out, int out_size)
{
    const float* x     = (const float*)d_in[0];  // [B,T,C]
    const float* w_qkv = (const float*)d_in[1];  // [C,3C]
    const float* b_qkv = (const float*)d_in[2];  // [3C]
    const float* w_o   = (const float*)d_in[3];  // [C,C]
    const float* b_o   = (const float*)d_in[4];  // [C]
    float* out = (float*)d_out;

    float *qkv_ptr, *att_ptr;
    cudaGetSymbolAddress((void**)&qkv_ptr, g_qkv);
    cudaGetSymbolAddress((void**)&att_ptr, g_att);

    const size_t o_elems    = (size_t)Bb * Tt * Cc;              // 4,194,304
    const size_t attn_elems = (size_t)Bb * Hh * Tt * (size_t)Tt; // 134,217,728
    int write_attn = ((size_t)out_size >= o_elems + attn_elems) ? 1 : 0;
    float* attn_w_ptr = write_attn ? (out + o_elems) : nullptr;

    // 1) QKV projection: [4096,1024] @ [1024,3072] + bias
    {
        dim3 grid(C3 / 64, BT / 64);
        gemm_bias_kernel<<<grid, 256>>>(x, w_qkv, b_qkv, qkv_ptr, BT, C3, Cc);
    }
    // 2) causal attention (+ attn_w materialization)
    {
        dim3 grid(Tt / 4, Hh, Bb);
        attn_kernel<<<grid, 128>>>(qkv_ptr, attn_w_ptr, att_ptr, write_attn);
    }
    // 3) output projection: [4096,1024] @ [1024,1024] + bias -> d_out[0:o_elems]
    {
        dim3 grid(Cc / 64, BT / 64);
        gemm_bias_kernel<<<grid, 256>>>(att_ptr, w_o, b_o, out, BT, Cc, Cc);
    }
}

// round 3
// speedup vs baseline: 5.9133x; 5.9133x over previous
#include <cuda_runtime.h>
#include <math.h>

#define Bb 2
#define Tt 2048
#define Cc 1024
#define Hh 16
#define Dd 64
#define BT (Bb*Tt)      // 4096
#define C3 (3*Cc)       // 3072
#define PAD 68          // 64 + 4 pad, keeps 16B alignment

// Scratch (allocation-free rule: __device__ globals)
__device__ float g_qkv[(size_t)BT * C3];           // [B,T,3C]
__device__ float g_att[(size_t)BT * Cc];           // attn_v in [B,T,C]
__device__ float g_ml[(size_t)Bb * Hh * Tt * 2];   // per-row (m,l)

// ---------------------------------------------------------------------------
// fp32 GEMM: out[M,N] = A[M,K] @ W[K,N] + bias[N]
// BM=BN=128, BK=8, 256 threads, 8x8 register tile per thread, float4 I/O.
// M,N,K divisible by 128/8 for this problem.
// ---------------------------------------------------------------------------
__global__ __launch_bounds__(256) void gemm128_kernel(
    const float* __restrict__ A, const float* __restrict__ W,
    const float* __restrict__ bias, float* __restrict__ out,
    int M, int N, int K)
{
    __shared__ float As[8][128];
    __shared__ float Bs[8][128];

    const int tid  = threadIdx.x;
    const int trow = tid >> 4;          // 0..15
    const int tcol = tid & 15;          // 0..15
    const int row0 = blockIdx.y * 128;
    const int col0 = blockIdx.x * 128;

    const int aRow = tid >> 1;          // 0..127
    const int aK   = (tid & 1) * 4;     // 0 or 4
    const int bK   = tid >> 5;          // 0..7
    const int bCol = (tid & 31) * 4;    // 0..124

    const float* Ap = A + (size_t)(row0 + aRow) * K + aK;
    const float* Wp = W + (size_t)bK * N + col0 + bCol;

    float acc[8][8];
#pragma unroll
    for (int i = 0; i < 8; i++)
#pragma unroll
        for (int j = 0; j < 8; j++) acc[i][j] = 0.f;

    for (int k0 = 0; k0 < K; k0 += 8) {
        float4 av = *(const float4*)(Ap + k0);
        As[aK + 0][aRow] = av.x;
        As[aK + 1][aRow] = av.y;
        As[aK + 2][aRow] = av.z;
        As[aK + 3][aRow] = av.w;
        *(float4*)&Bs[bK][bCol] = *(const float4*)(Wp + (size_t)k0 * N);
        __syncthreads();

#pragma unroll
        for (int kk = 0; kk < 8; kk++) {
            float4 a0 = *(const float4*)&As[kk][trow * 8];
            float4 a1 = *(const float4*)&As[kk][trow * 8 + 4];
            float4 b0 = *(const float4*)&Bs[kk][tcol * 8];
            float4 b1 = *(const float4*)&Bs[kk][tcol * 8 + 4];
            float a[8] = {a0.x, a0.y, a0.z, a0.w, a1.x, a1.y, a1.z, a1.w};
            float b[8] = {b0.x, b0.y, b0.z, b0.w, b1.x, b1.y, b1.z, b1.w};
#pragma unroll
            for (int i = 0; i < 8; i++)
#pragma unroll
                for (int j = 0; j < 8; j++) acc[i][j] += a[i] * b[j];
        }
        __syncthreads();
    }

#pragma unroll
    for (int i = 0; i < 8; i++) {
        int r = row0 + trow * 8 + i;
        float* op = out + (size_t)r * N + col0 + tcol * 8;
        const float* bp = bias + col0 + tcol * 8;
#pragma unroll
        for (int j = 0; j < 8; j += 4) {
            float4 v;
            v.x = acc[i][j + 0] + bp[j + 0];
            v.y = acc[i][j + 1] + bp[j + 1];
            v.z = acc[i][j + 2] + bp[j + 2];
            v.w = acc[i][j + 3] + bp[j + 3];
            *(float4*)(op + j) = v;
        }
    }
}

// ---------------------------------------------------------------------------
// Tiled flash-style causal attention. One block = (b, h, 64-query tile).
// Per key tile of 64: S = Q K^T (register-tiled), raw scores stored to attn_w,
// online softmax stats, P V accumulated. Per-row (m, l) stored for the
// normalization kernel. 256 threads, 4x4 register tiles.
// ---------------------------------------------------------------------------
__global__ __launch_bounds__(256) void attn_tile_kernel(
    const float* __restrict__ qkv,
    float* __restrict__ attn_w,          // raw scores out (may be null)
    float* __restrict__ att_out,         // [B,T,C]
    float* __restrict__ ml,
    int write_attn)
{
    extern __shared__ float sm[];
    float* Qs = sm;                      // [64][PAD], d-major: Qs[d][q]
    float* Ks = sm + 64 * PAD;           // [64][PAD], d-major: Ks[d][j]; reused as Ps[j][q]
    float* Vs = sm + 2 * 64 * PAD;       // [64][PAD], j-major: Vs[j][d]

    const int tid  = threadIdx.x;
    const int trow = tid >> 4;           // 0..15  (query rows trow*4..+3)
    const int tcol = tid & 15;           // 0..15  (cols tcol*4..+3)
    const int qt = (Tt / 64 - 1) - blockIdx.x;   // heavy tiles first
    const int h  = blockIdx.y;
    const int b  = blockIdx.z;
    const int q0 = qt * 64;
    const float scale = 0.125f;

    const float* Qg = qkv + ((size_t)b * Tt + q0) * C3 + h * Dd;
    const float* Kg = qkv + (size_t)b * Tt * C3 + Cc + h * Dd;
    const float* Vg = qkv + (size_t)b * Tt * C3 + 2 * Cc + h * Dd;

    // load Q tile transposed: Qs[d][q]
    for (int idx = tid; idx < 4096; idx += 256) {
        int q = idx >> 6, d = idx & 63;
        Qs[d * PAD + q] = Qg[(size_t)q * C3 + d];
    }

    float m[4], l[4], O[4][4];
#pragma unroll
    for (int i = 0; i < 4; i++) {
        m[i] = -1e30f; l[i] = 0.f;
#pragma unroll
        for (int j = 0; j < 4; j++) O[i][j] = 0.f;
    }

    for (int kt = 0; kt <= qt; kt++) {
        const int j0 = kt * 64;
        for (int idx = tid; idx < 4096; idx += 256) {
            int j = idx >> 6, d = idx & 63;
            float kvK = Kg[(size_t)(j0 + j) * C3 + d];
            float kvV = Vg[(size_t)(j0 + j) * C3 + d];
            Ks[d * PAD + j] = kvK;
            Vs[j * PAD + d] = kvV;
        }
        __syncthreads();

        // S = Q K^T  (inner dim = d)
        float acc[4][4];
#pragma unroll
        for (int i = 0; i < 4; i++)
#pragma unroll
            for (int j = 0; j < 4; j++) acc[i][j] = 0.f;
#pragma unroll
        for (int d = 0; d < 64; d++) {
            float4 a = *(const float4*)&Qs[d * PAD + trow * 4];
            float4 bb = *(const float4*)&Ks[d * PAD + tcol * 4];
            float av[4] = {a.x, a.y, a.z, a.w};
            float bv[4] = {bb.x, bb.y, bb.z, bb.w};
#pragma unroll
            for (int i = 0; i < 4; i++)
#pragma unroll
                for (int j = 0; j < 4; j++) acc[i][j] += av[i] * bv[j];
        }

        // scale + causal mask (only diagonal tile needs it: j0==q0 there)
#pragma unroll
        for (int i = 0; i < 4; i++)
#pragma unroll
            for (int j = 0; j < 4; j++) {
                acc[i][j] *= scale;
                if (kt == qt && (j0 + tcol * 4 + j) > (q0 + trow * 4 + i))
                    acc[i][j] = -1e30f;
            }

        // write raw scores
        if (write_attn) {
#pragma unroll
            for (int i = 0; i < 4; i++) {
                float* wp = attn_w +
                    ((size_t)(b * Hh + h) * Tt + q0 + trow * 4 + i) * (size_t)Tt +
                    j0 + tcol * 4;
                float4 v = {acc[i][0], acc[i][1], acc[i][2], acc[i][3]};
                *(float4*)wp = v;
            }
        }

        // online softmax update
#pragma unroll
        for (int i = 0; i < 4; i++) {
            float tm = fmaxf(fmaxf(acc[i][0], acc[i][1]), fmaxf(acc[i][2], acc[i][3]));
#pragma unroll
            for (int off = 8; off; off >>= 1)
                tm = fmaxf(tm, __shfl_xor_sync(0xffffffffu, tm, off));
            float mn = fmaxf(m[i], tm);
            float f = __expf(m[i] - mn);
            float rs = 0.f;
#pragma unroll
            for (int j = 0; j < 4; j++) {
                acc[i][j] = __expf(acc[i][j] - mn);
                rs += acc[i][j];
            }
#pragma unroll
            for (int off = 8; off; off >>= 1)
                rs += __shfl_xor_sync(0xffffffffu, rs, off);
            l[i] = l[i] * f + rs;
            m[i] = mn;
#pragma unroll
            for (int j = 0; j < 4; j++) O[i][j] *= f;
        }
        __syncthreads();   // everyone done reading Ks before overwriting as Ps

        // Ps[j][q] = P (alias of Ks)
#pragma unroll
        for (int i = 0; i < 4; i++)
#pragma unroll
            for (int j = 0; j < 4; j++)
                Ks[(tcol * 4 + j) * PAD + trow * 4 + i] = acc[i][j];
        __syncthreads();

        // O += P V (inner dim = j)
#pragma unroll
        for (int jj = 0; jj < 64; jj++) {
            float4 a = *(const float4*)&Ks[jj * PAD + trow * 4];
            float4 bb = *(const float4*)&Vs[jj * PAD + tcol * 4];
            float av[4] = {a.x, a.y, a.z, a.w};
            float bv[4] = {bb.x, bb.y, bb.z, bb.w};
#pragma unroll
            for (int i = 0; i < 4; i++)
#pragma unroll
                for (int j = 0; j < 4; j++) O[i][j] += av[i] * bv[j];
        }
        __syncthreads();
    }

    // epilogue: normalize O, write att_out and (m,l)
#pragma unroll
    for (int i = 0; i < 4; i++) {
        float invl = 1.f / l[i];
        float* op = att_out + ((size_t)b * Tt + q0 + trow * 4 + i) * Cc + h * Dd + tcol * 4;
        float4 v = {O[i][0] * invl, O[i][1] * invl, O[i][2] * invl, O[i][3] * invl};
        *(float4*)op = v;
    }
    if (tcol == 0) {
#pragma unroll
        for (int i = 0; i < 4; i++) {
            size_t row = (size_t)(b * Hh + h) * Tt + q0 + trow * 4 + i;
            ml[row * 2]     = m[i];
            ml[row * 2 + 1] = l[i];
        }
    }
}

// ---------------------------------------------------------------------------
// Normalization: attn_w[row][j] = (j<=q) ? exp(s - m)/l : 0. One block per row.
// ---------------------------------------------------------------------------
__global__ __launch_bounds__(256) void attn_norm_kernel(
    float* __restrict__ attn_w, const float* __restrict__ ml)
{
    const int row = blockIdx.x;            // 0 .. B*H*T-1
    const int q = row & (Tt - 1);
    const float mrow = ml[(size_t)row * 2];
    const float invl = 1.f / ml[(size_t)row * 2 + 1];
    float* base = attn_w + (size_t)row * Tt;

    for (int c0 = threadIdx.x * 4; c0 < Tt; c0 += 256 * 4) {
        float4 s = *(const float4*)(base + c0);
        float4 w;
        w.x = (c0 + 0 > q) ? 0.f : __expf(s.x - mrow) * invl;
        w.y = (c0 + 1 > q) ? 0.f : __expf(s.y - mrow) * invl;
        w.z = (c0 + 2 > q) ? 0.f : __expf(s.z - mrow) * invl;
        w.w = (c0 + 3 > q) ? 0.f : __expf(s.w - mrow) * invl;
        *(float4*)(base + c0) = w;
    }
}

// ---------------------------------------------------------------------------
extern "C" void kernel_launch(void* const* d_in, const int* in_sizes, int n_in,
                              void* d_out, int out_size)
{
    const float* x     = (const float*)d_in[0];
    const float* w_qkv = (const float*)d_in[1];
    const float* b_qkv = (const float*)d_in[2];
    const float* w_o   = (const float*)d_in[3];
    const float* b_o   = (const float*)d_in[4];
    float* out = (float*)d_out;

    float *qkv_ptr, *att_ptr, *ml_ptr;
    cudaGetSymbolAddress((void**)&qkv_ptr, g_qkv);
    cudaGetSymbolAddress((void**)&att_ptr, g_att);
    cudaGetSymbolAddress((void**)&ml_ptr, g_ml);

    const size_t o_elems    = (size_t)Bb * Tt * Cc;
    const size_t attn_elems = (size_t)Bb * Hh * Tt * (size_t)Tt;
    int write_attn = ((size_t)out_size >= o_elems + attn_elems) ? 1 : 0;
    float* attn_w_ptr = write_attn ? (out + o_elems) : nullptr;

    const int attn_smem = 3 * 64 * PAD * sizeof(float);   // 52224 B
    cudaFuncSetAttribute(attn_tile_kernel,
                         cudaFuncAttributeMaxDynamicSharedMemorySize, attn_smem);

    // 1) QKV projection
    {
        dim3 grid(C3 / 128, BT / 128);
        gemm128_kernel<<<grid, 256>>>(x, w_qkv, b_qkv, qkv_ptr, BT, C3, Cc);
    }
    // 2) causal attention (raw scores + m,l + attn_v)
    {
        dim3 grid(Tt / 64, Hh, Bb);
        attn_tile_kernel<<<grid, 256, attn_smem>>>(qkv_ptr, attn_w_ptr, att_ptr,
                                                   ml_ptr, write_attn);
    }
    // 3) normalize attn_w
    if (write_attn) {
        attn_norm_kernel<<<Bb * Hh * Tt, 256>>>(attn_w_ptr, ml_ptr);
    }
    // 4) output projection
    {
        dim3 grid(Cc / 128, BT / 128);
        gemm128_kernel<<<grid, 256>>>(att_ptr, w_o, b_o, out, BT, Cc, Cc);
    }
}

// round 6
// speedup vs baseline: 8.7759x; 1.4841x over previous
#include <cuda_runtime.h>
#include <math.h>

#define Bb 2
#define Tt 2048
#define Cc 1024
#define Hh 16
#define Dd 64
#define BT (Bb*Tt)      // 4096
#define C3 (3*Cc)       // 3072
#define PAD 68

// Scratch (allocation-free rule: __device__ globals)
__device__ float g_qkv[(size_t)BT * C3];           // [B,T,3C]
__device__ float g_att[(size_t)BT * Cc];           // attn_v in [B,T,C]
__device__ float g_ml[(size_t)Bb * Hh * Tt * 2];   // per-row (m,l)

__device__ __forceinline__ unsigned f2tf(float x) {
    unsigned r;
    asm("cvt.rna.tf32.f32 %0, %1;" : "=r"(r) : "f"(x));
    return r;
}

// ---------------------------------------------------------------------------
// TF32 tensor-core GEMM: out[M,N] = A[M,K] @ W[K,N] + bias[N]
// BM=BN=128, BK=16. 8 warps (2x4), warp tile 64x32, mma.sync m16n8k8.
// M,N multiples of 128; K multiple of 16.
// ---------------------------------------------------------------------------
__global__ __launch_bounds__(256) void gemm_tc_kernel(
    const float* __restrict__ A, const float* __restrict__ W,
    const float* __restrict__ bias, float* __restrict__ out,
    int M, int N, int K)
{
    __shared__ unsigned As[128][20];   // [m][k], pad 4 -> conflict-free frags
    __shared__ unsigned Bs[16][132];   // [k][n], pad 4

    const int tid  = threadIdx.x;
    const int warp = tid >> 5, lane = tid & 31;
    const int gID  = lane >> 2, tig = lane & 3;
    const int wm = (warp >> 2) * 64;       // 0 / 64
    const int wn = (warp & 3) * 32;        // 0..96
    const int row0 = blockIdx.y * 128;
    const int col0 = blockIdx.x * 128;

    // global-load assignments
    const int aR = tid >> 2;               // 0..63 (and +64)
    const int aK = (tid & 3) * 4;          // 0,4,8,12
    const int bK = tid >> 4;               // 0..15
    const int bN = (tid & 15) * 8;         // 0..120

    const float* Ap  = A + (size_t)(row0 + aR) * K + aK;
    const float* Ap2 = Ap + (size_t)64 * K;
    const float* Wp  = W + (size_t)bK * N + col0 + bN;

    float acc[4][4][4];
#pragma unroll
    for (int mt = 0; mt < 4; mt++)
#pragma unroll
        for (int nt = 0; nt < 4; nt++)
#pragma unroll
            for (int i = 0; i < 4; i++) acc[mt][nt][i] = 0.f;

    const int ntile = K / 16;

    // preload tile 0
    float4 pa0 = *(const float4*)(Ap);
    float4 pa1 = *(const float4*)(Ap2);
    float4 pb0 = *(const float4*)(Wp);
    float4 pb1 = *(const float4*)(Wp + 4);

    As[aR][aK+0] = f2tf(pa0.x); As[aR][aK+1] = f2tf(pa0.y);
    As[aR][aK+2] = f2tf(pa0.z); As[aR][aK+3] = f2tf(pa0.w);
    As[aR+64][aK+0] = f2tf(pa1.x); As[aR+64][aK+1] = f2tf(pa1.y);
    As[aR+64][aK+2] = f2tf(pa1.z); As[aR+64][aK+3] = f2tf(pa1.w);
    Bs[bK][bN+0] = f2tf(pb0.x); Bs[bK][bN+1] = f2tf(pb0.y);
    Bs[bK][bN+2] = f2tf(pb0.z); Bs[bK][bN+3] = f2tf(pb0.w);
    Bs[bK][bN+4] = f2tf(pb1.x); Bs[bK][bN+5] = f2tf(pb1.y);
    Bs[bK][bN+6] = f2tf(pb1.z); Bs[bK][bN+7] = f2tf(pb1.w);

    for (int t = 0; t < ntile; t++) {
        __syncthreads();

        if (t + 1 < ntile) {
            int k0 = (t + 1) * 16;
            pa0 = *(const float4*)(Ap + k0);
            pa1 = *(const float4*)(Ap2 + k0);
            pb0 = *(const float4*)(Wp + (size_t)k0 * N);
            pb1 = *(const float4*)(Wp + (size_t)k0 * N + 4);
        }

#pragma unroll
        for (int ks = 0; ks < 16; ks += 8) {
            unsigned af[4][4], bf[4][2];
#pragma unroll
            for (int mt = 0; mt < 4; mt++) {
                int r = wm + mt * 16 + gID;
                af[mt][0] = As[r][ks + tig];
                af[mt][1] = As[r + 8][ks + tig];
                af[mt][2] = As[r][ks + tig + 4];
                af[mt][3] = As[r + 8][ks + tig + 4];
            }
#pragma unroll
            for (int nt = 0; nt < 4; nt++) {
                int c = wn + nt * 8 + gID;
                bf[nt][0] = Bs[ks + tig][c];
                bf[nt][1] = Bs[ks + tig + 4][c];
            }
#pragma unroll
            for (int mt = 0; mt < 4; mt++)
#pragma unroll
                for (int nt = 0; nt < 4; nt++) {
                    asm volatile(
                        "mma.sync.aligned.m16n8k8.row.col.f32.tf32.tf32.f32 "
                        "{%0,%1,%2,%3}, {%4,%5,%6,%7}, {%8,%9}, {%0,%1,%2,%3};"
                        : "+f"(acc[mt][nt][0]), "+f"(acc[mt][nt][1]),
                          "+f"(acc[mt][nt][2]), "+f"(acc[mt][nt][3])
                        : "r"(af[mt][0]), "r"(af[mt][1]), "r"(af[mt][2]), "r"(af[mt][3]),
                          "r"(bf[nt][0]), "r"(bf[nt][1]));
                }
        }
        __syncthreads();

        if (t + 1 < ntile) {
            As[aR][aK+0] = f2tf(pa0.x); As[aR][aK+1] = f2tf(pa0.y);
            As[aR][aK+2] = f2tf(pa0.z); As[aR][aK+3] = f2tf(pa0.w);
            As[aR+64][aK+0] = f2tf(pa1.x); As[aR+64][aK+1] = f2tf(pa1.y);
            As[aR+64][aK+2] = f2tf(pa1.z); As[aR+64][aK+3] = f2tf(pa1.w);
            Bs[bK][bN+0] = f2tf(pb0.x); Bs[bK][bN+1] = f2tf(pb0.y);
            Bs[bK][bN+2] = f2tf(pb0.z); Bs[bK][bN+3] = f2tf(pb0.w);
            Bs[bK][bN+4] = f2tf(pb1.x); Bs[bK][bN+5] = f2tf(pb1.y);
            Bs[bK][bN+6] = f2tf(pb1.z); Bs[bK][bN+7] = f2tf(pb1.w);
        }
    }

    // epilogue: acc + bias -> out
#pragma unroll
    for (int mt = 0; mt < 4; mt++) {
        int r = row0 + wm + mt * 16 + gID;
#pragma unroll
        for (int nt = 0; nt < 4; nt++) {
            int c = col0 + wn + nt * 8 + 2 * tig;
            float b0v = bias[c], b1v = bias[c + 1];
            float2 v0 = {acc[mt][nt][0] + b0v, acc[mt][nt][1] + b1v};
            float2 v1 = {acc[mt][nt][2] + b0v, acc[mt][nt][3] + b1v};
            *(float2*)(out + (size_t)r * N + c) = v0;
            *(float2*)(out + (size_t)(r + 8) * N + c) = v1;
        }
    }
}

// ---------------------------------------------------------------------------
// Tiled flash-style causal attention (fp32). One block = (b, h, 64-query tile).
// ---------------------------------------------------------------------------
__global__ __launch_bounds__(256) void attn_tile_kernel(
    const float* __restrict__ qkv,
    float* __restrict__ attn_w,
    float* __restrict__ att_out,
    float* __restrict__ ml,
    int write_attn)
{
    extern __shared__ float sm[];
    float* Qs = sm;                      // [64][PAD], d-major
    float* Ks = sm + 64 * PAD;           // [64][PAD], d-major; reused as Ps
    float* Vs = sm + 2 * 64 * PAD;       // [64][PAD], j-major

    const int tid  = threadIdx.x;
    const int trow = tid >> 4;
    const int tcol = tid & 15;
    const int qt = (Tt / 64 - 1) - blockIdx.x;
    const int h  = blockIdx.y;
    const int b  = blockIdx.z;
    const int q0 = qt * 64;
    const float scale = 0.125f;

    const float* Qg = qkv + ((size_t)b * Tt + q0) * C3 + h * Dd;
    const float* Kg = qkv + (size_t)b * Tt * C3 + Cc + h * Dd;
    const float* Vg = qkv + (size_t)b * Tt * C3 + 2 * Cc + h * Dd;

    for (int idx = tid; idx < 4096; idx += 256) {
        int q = idx >> 6, d = idx & 63;
        Qs[d * PAD + q] = Qg[(size_t)q * C3 + d];
    }

    float m[4], l[4], O[4][4];
#pragma unroll
    for (int i = 0; i < 4; i++) {
        m[i] = -1e30f; l[i] = 0.f;
#pragma unroll
        for (int j = 0; j < 4; j++) O[i][j] = 0.f;
    }

    for (int kt = 0; kt <= qt; kt++) {
        const int j0 = kt * 64;
        for (int idx = tid; idx < 4096; idx += 256) {
            int j = idx >> 6, d = idx & 63;
            Ks[d * PAD + j] = Kg[(size_t)(j0 + j) * C3 + d];
            Vs[j * PAD + d] = Vg[(size_t)(j0 + j) * C3 + d];
        }
        __syncthreads();

        float acc[4][4];
#pragma unroll
        for (int i = 0; i < 4; i++)
#pragma unroll
            for (int j = 0; j < 4; j++) acc[i][j] = 0.f;
#pragma unroll
        for (int d = 0; d < 64; d++) {
            float4 a = *(const float4*)&Qs[d * PAD + trow * 4];
            float4 bb = *(const float4*)&Ks[d * PAD + tcol * 4];
            float av[4] = {a.x, a.y, a.z, a.w};
            float bv[4] = {bb.x, bb.y, bb.z, bb.w};
#pragma unroll
            for (int i = 0; i < 4; i++)
#pragma unroll
                for (int j = 0; j < 4; j++) acc[i][j] += av[i] * bv[j];
        }

#pragma unroll
        for (int i = 0; i < 4; i++)
#pragma unroll
            for (int j = 0; j < 4; j++) {
                acc[i][j] *= scale;
                if (kt == qt && (j0 + tcol * 4 + j) > (q0 + trow * 4 + i))
                    acc[i][j] = -1e30f;
            }

        if (write_attn) {
#pragma unroll
            for (int i = 0; i < 4; i++) {
                float* wp = attn_w +
                    ((size_t)(b * Hh + h) * Tt + q0 + trow * 4 + i) * (size_t)Tt +
                    j0 + tcol * 4;
                float4 v = {acc[i][0], acc[i][1], acc[i][2], acc[i][3]};
                *(float4*)wp = v;
            }
        }

#pragma unroll
        for (int i = 0; i < 4; i++) {
            float tm = fmaxf(fmaxf(acc[i][0], acc[i][1]), fmaxf(acc[i][2], acc[i][3]));
#pragma unroll
            for (int off = 8; off; off >>= 1)
                tm = fmaxf(tm, __shfl_xor_sync(0xffffffffu, tm, off));
            float mn = fmaxf(m[i], tm);
            float f = __expf(m[i] - mn);
            float rs = 0.f;
#pragma unroll
            for (int j = 0; j < 4; j++) {
                acc[i][j] = __expf(acc[i][j] - mn);
                rs += acc[i][j];
            }
#pragma unroll
            for (int off = 8; off; off >>= 1)
                rs += __shfl_xor_sync(0xffffffffu, rs, off);
            l[i] = l[i] * f + rs;
            m[i] = mn;
#pragma unroll
            for (int j = 0; j < 4; j++) O[i][j] *= f;
        }
        __syncthreads();

#pragma unroll
        for (int i = 0; i < 4; i++)
#pragma unroll
            for (int j = 0; j < 4; j++)
                Ks[(tcol * 4 + j) * PAD + trow * 4 + i] = acc[i][j];
        __syncthreads();

#pragma unroll
        for (int jj = 0; jj < 64; jj++) {
            float4 a = *(const float4*)&Ks[jj * PAD + trow * 4];
            float4 bb = *(const float4*)&Vs[jj * PAD + tcol * 4];
            float av[4] = {a.x, a.y, a.z, a.w};
            float bv[4] = {bb.x, bb.y, bb.z, bb.w};
#pragma unroll
            for (int i = 0; i < 4; i++)
#pragma unroll
                for (int j = 0; j < 4; j++) O[i][j] += av[i] * bv[j];
        }
        __syncthreads();
    }

#pragma unroll
    for (int i = 0; i < 4; i++) {
        float invl = 1.f / l[i];
        float* op = att_out + ((size_t)b * Tt + q0 + trow * 4 + i) * Cc + h * Dd + tcol * 4;
        float4 v = {O[i][0] * invl, O[i][1] * invl, O[i][2] * invl, O[i][3] * invl};
        *(float4*)op = v;
    }
    if (tcol == 0) {
#pragma unroll
        for (int i = 0; i < 4; i++) {
            size_t row = (size_t)(b * Hh + h) * Tt + q0 + trow * 4 + i;
            ml[row * 2]     = m[i];
            ml[row * 2 + 1] = l[i];
        }
    }
}

// ---------------------------------------------------------------------------
// Normalization: only READ the causal (written) region; write zeros elsewhere.
// ---------------------------------------------------------------------------
__global__ __launch_bounds__(256) void attn_norm_kernel(
    float* __restrict__ attn_w, const float* __restrict__ ml)
{
    const int row = blockIdx.x;
    const int q = row & (Tt - 1);
    const float mrow = ml[(size_t)row * 2];
    const float invl = 1.f / ml[(size_t)row * 2 + 1];
    float* base = attn_w + (size_t)row * Tt;

    for (int c0 = threadIdx.x * 4; c0 < Tt; c0 += 256 * 4) {
        if (c0 > q) {
            float4 z = {0.f, 0.f, 0.f, 0.f};
            *(float4*)(base + c0) = z;
        } else {
            float4 s = *(const float4*)(base + c0);
            float4 w;
            w.x = (c0 + 0 > q) ? 0.f : __expf(s.x - mrow) * invl;
            w.y = (c0 + 1 > q) ? 0.f : __expf(s.y - mrow) * invl;
            w.z = (c0 + 2 > q) ? 0.f : __expf(s.z - mrow) * invl;
            w.w = (c0 + 3 > q) ? 0.f : __expf(s.w - mrow) * invl;
            *(float4*)(base + c0) = w;
        }
    }
}

// ---------------------------------------------------------------------------
extern "C" void kernel_launch(void* const* d_in, const int* in_sizes, int n_in,
                              void* d_out, int out_size)
{
    const float* x     = (const float*)d_in[0];
    const float* w_qkv = (const float*)d_in[1];
    const float* b_qkv = (const float*)d_in[2];
    const float* w_o   = (const float*)d_in[3];
    const float* b_o   = (const float*)d_in[4];
    float* out = (float*)d_out;

    float *qkv_ptr, *att_ptr, *ml_ptr;
    cudaGetSymbolAddress((void**)&qkv_ptr, g_qkv);
    cudaGetSymbolAddress((void**)&att_ptr, g_att);
    cudaGetSymbolAddress((void**)&ml_ptr, g_ml);

    const size_t o_elems    = (size_t)Bb * Tt * Cc;
    const size_t attn_elems = (size_t)Bb * Hh * Tt * (size_t)Tt;
    int write_attn = ((size_t)out_size >= o_elems + attn_elems) ? 1 : 0;
    float* attn_w_ptr = write_attn ? (out + o_elems) : nullptr;

    const int attn_smem = 3 * 64 * PAD * sizeof(float);
    cudaFuncSetAttribute(attn_tile_kernel,
                         cudaFuncAttributeMaxDynamicSharedMemorySize, attn_smem);

    // 1) QKV projection (tf32 tensor cores)
    {
        dim3 grid(C3 / 128, BT / 128);
        gemm_tc_kernel<<<grid, 256>>>(x, w_qkv, b_qkv, qkv_ptr, BT, C3, Cc);
    }
    // 2) causal attention (raw scores + m,l + attn_v)
    {
        dim3 grid(Tt / 64, Hh, Bb);
        attn_tile_kernel<<<grid, 256, attn_smem>>>(qkv_ptr, attn_w_ptr, att_ptr,
                                                   ml_ptr, write_attn);
    }
    // 3) normalize attn_w
    if (write_attn) {
        attn_norm_kernel<<<Bb * Hh * Tt, 256>>>(attn_w_ptr, ml_ptr);
    }
    // 4) output projection (tf32 tensor cores)
    {
        dim3 grid(Cc / 128, BT / 128);
        gemm_tc_kernel<<<grid, 256>>>(att_ptr, w_o, b_o, out, BT, Cc, Cc);
    }
}

// round 8
// speedup vs baseline: 11.9620x; 1.3630x over previous
#include <cuda_runtime.h>
#include <math.h>

#define Bb 2
#define Tt 2048
#define Cc 1024
#define Hh 16
#define Dd 64
#define BT (Bb*Tt)      // 4096
#define C3 (3*Cc)       // 3072
#define SPAD 68

// Scratch (allocation-free rule: __device__ globals)
__device__ float g_qkv[(size_t)BT * C3];           // [B,T,3C]
__device__ float g_att[(size_t)BT * Cc];           // attn_v in [B,T,C]
__device__ float g_ml[(size_t)Bb * Hh * Tt * 2];   // per-row (m,l)

__device__ __forceinline__ unsigned f2tf(float x) {
    unsigned r;
    asm("cvt.rna.tf32.f32 %0, %1;" : "=r"(r) : "f"(x));
    return r;
}

#define MMA_TF32(c, a0,a1,a2,a3, b0,b1)                                   \
    asm volatile(                                                          \
        "mma.sync.aligned.m16n8k8.row.col.f32.tf32.tf32.f32 "             \
        "{%0,%1,%2,%3}, {%4,%5,%6,%7}, {%8,%9}, {%0,%1,%2,%3};"           \
        : "+f"((c)[0]), "+f"((c)[1]), "+f"((c)[2]), "+f"((c)[3])          \
        : "r"(a0), "r"(a1), "r"(a2), "r"(a3), "r"(b0), "r"(b1))

// ---------------------------------------------------------------------------
// TF32 tensor-core GEMM: out[M,N] = A[M,K] @ W[K,N] + bias[N]  (unchanged)
// ---------------------------------------------------------------------------
__global__ __launch_bounds__(256) void gemm_tc_kernel(
    const float* __restrict__ A, const float* __restrict__ W,
    const float* __restrict__ bias, float* __restrict__ out,
    int M, int N, int K)
{
    __shared__ unsigned As[128][20];
    __shared__ unsigned Bs[16][132];

    const int tid  = threadIdx.x;
    const int warp = tid >> 5, lane = tid & 31;
    const int gID  = lane >> 2, tig = lane & 3;
    const int wm = (warp >> 2) * 64;
    const int wn = (warp & 3) * 32;
    const int row0 = blockIdx.y * 128;
    const int col0 = blockIdx.x * 128;

    const int aR = tid >> 2;
    const int aK = (tid & 3) * 4;
    const int bK = tid >> 4;
    const int bN = (tid & 15) * 8;

    const float* Ap  = A + (size_t)(row0 + aR) * K + aK;
    const float* Ap2 = Ap + (size_t)64 * K;
    const float* Wp  = W + (size_t)bK * N + col0 + bN;

    float acc[4][4][4];
#pragma unroll
    for (int mt = 0; mt < 4; mt++)
#pragma unroll
        for (int nt = 0; nt < 4; nt++)
#pragma unroll
            for (int i = 0; i < 4; i++) acc[mt][nt][i] = 0.f;

    const int ntile = K / 16;

    float4 pa0 = *(const float4*)(Ap);
    float4 pa1 = *(const float4*)(Ap2);
    float4 pb0 = *(const float4*)(Wp);
    float4 pb1 = *(const float4*)(Wp + 4);

    As[aR][aK+0] = f2tf(pa0.x); As[aR][aK+1] = f2tf(pa0.y);
    As[aR][aK+2] = f2tf(pa0.z); As[aR][aK+3] = f2tf(pa0.w);
    As[aR+64][aK+0] = f2tf(pa1.x); As[aR+64][aK+1] = f2tf(pa1.y);
    As[aR+64][aK+2] = f2tf(pa1.z); As[aR+64][aK+3] = f2tf(pa1.w);
    Bs[bK][bN+0] = f2tf(pb0.x); Bs[bK][bN+1] = f2tf(pb0.y);
    Bs[bK][bN+2] = f2tf(pb0.z); Bs[bK][bN+3] = f2tf(pb0.w);
    Bs[bK][bN+4] = f2tf(pb1.x); Bs[bK][bN+5] = f2tf(pb1.y);
    Bs[bK][bN+6] = f2tf(pb1.z); Bs[bK][bN+7] = f2tf(pb1.w);

    for (int t = 0; t < ntile; t++) {
        __syncthreads();

        if (t + 1 < ntile) {
            int k0 = (t + 1) * 16;
            pa0 = *(const float4*)(Ap + k0);
            pa1 = *(const float4*)(Ap2 + k0);
            pb0 = *(const float4*)(Wp + (size_t)k0 * N);
            pb1 = *(const float4*)(Wp + (size_t)k0 * N + 4);
        }

#pragma unroll
        for (int ks = 0; ks < 16; ks += 8) {
            unsigned af[4][4], bf[4][2];
#pragma unroll
            for (int mt = 0; mt < 4; mt++) {
                int r = wm + mt * 16 + gID;
                af[mt][0] = As[r][ks + tig];
                af[mt][1] = As[r + 8][ks + tig];
                af[mt][2] = As[r][ks + tig + 4];
                af[mt][3] = As[r + 8][ks + tig + 4];
            }
#pragma unroll
            for (int nt = 0; nt < 4; nt++) {
                int c = wn + nt * 8 + gID;
                bf[nt][0] = Bs[ks + tig][c];
                bf[nt][1] = Bs[ks + tig + 4][c];
            }
#pragma unroll
            for (int mt = 0; mt < 4; mt++)
#pragma unroll
                for (int nt = 0; nt < 4; nt++)
                    MMA_TF32(acc[mt][nt], af[mt][0], af[mt][1], af[mt][2], af[mt][3],
                             bf[nt][0], bf[nt][1]);
        }
        __syncthreads();

        if (t + 1 < ntile) {
            As[aR][aK+0] = f2tf(pa0.x); As[aR][aK+1] = f2tf(pa0.y);
            As[aR][aK+2] = f2tf(pa0.z); As[aR][aK+3] = f2tf(pa0.w);
            As[aR+64][aK+0] = f2tf(pa1.x); As[aR+64][aK+1] = f2tf(pa1.y);
            As[aR+64][aK+2] = f2tf(pa1.z); As[aR+64][aK+3] = f2tf(pa1.w);
            Bs[bK][bN+0] = f2tf(pb0.x); Bs[bK][bN+1] = f2tf(pb0.y);
            Bs[bK][bN+2] = f2tf(pb0.z); Bs[bK][bN+3] = f2tf(pb0.w);
            Bs[bK][bN+4] = f2tf(pb1.x); Bs[bK][bN+5] = f2tf(pb1.y);
            Bs[bK][bN+6] = f2tf(pb1.z); Bs[bK][bN+7] = f2tf(pb1.w);
        }
    }

#pragma unroll
    for (int mt = 0; mt < 4; mt++) {
        int r = row0 + wm + mt * 16 + gID;
#pragma unroll
        for (int nt = 0; nt < 4; nt++) {
            int c = col0 + wn + nt * 8 + 2 * tig;
            float b0v = bias[c], b1v = bias[c + 1];
            float2 v0 = {acc[mt][nt][0] + b0v, acc[mt][nt][1] + b1v};
            float2 v1 = {acc[mt][nt][2] + b0v, acc[mt][nt][3] + b1v};
            *(float2*)(out + (size_t)r * N + c) = v0;
            *(float2*)(out + (size_t)(r + 8) * N + c) = v1;
        }
    }
}

// ---------------------------------------------------------------------------
// TF32 tensor-core flash attention. Block = (b, h, 128-query tile), 8 warps.
// Warp w owns rows w*16..w*16+15 (full 64-col span) -> softmax reductions are
// 4-lane quad shuffles. K-tiles of 64. Raw scores streamed to attn_w; (m,l)
// saved for the separate normalization pass. Scale folded into Q (exact).
// ---------------------------------------------------------------------------
__global__ __launch_bounds__(256) void attn_tc_kernel(
    const float* __restrict__ qkv,
    float* __restrict__ attn_w,
    float* __restrict__ att_out,
    float* __restrict__ ml,
    int write_attn)
{
    extern __shared__ unsigned smu[];
    unsigned* Qs = smu;                  // [128][SPAD]  Q[q][d] (pre-scaled)
    unsigned* Ks = Qs + 128 * SPAD;      // [64][SPAD]   K[j][d]
    unsigned* Vs = Ks + 64 * SPAD;       // [64][SPAD]   V[j][d]
    unsigned* Ps = Vs + 64 * SPAD;       // [128][SPAD]  P[q][j]

    const int tid  = threadIdx.x;
    const int warp = tid >> 5, lane = tid & 31;
    const int gID  = lane >> 2, tig = lane & 3;
    const int qt = (Tt / 128 - 1) - blockIdx.x;   // heavy tiles first
    const int h  = blockIdx.y;
    const int b  = blockIdx.z;
    const int q0 = qt * 128;
    const int row_w = warp * 16;

    const float* Qg = qkv + ((size_t)b * Tt + q0) * C3 + h * Dd;
    const float* Kg = qkv + (size_t)b * Tt * C3 + Cc + h * Dd;
    const float* Vg = qkv + (size_t)b * Tt * C3 + 2 * Cc + h * Dd;

    // Q tile 128x64, scaled by 1/8 (exact power of 2)
    for (int idx = tid; idx < 2048; idx += 256) {
        int q = idx >> 4, dc = (idx & 15) << 2;
        float4 v = *(const float4*)(Qg + (size_t)q * C3 + dc);
        unsigned* p = Qs + q * SPAD + dc;
        p[0] = f2tf(v.x * 0.125f); p[1] = f2tf(v.y * 0.125f);
        p[2] = f2tf(v.z * 0.125f); p[3] = f2tf(v.w * 0.125f);
    }

    float m0 = -1e30f, m1 = -1e30f, l0 = 0.f, l1 = 0.f;
    float o[8][4];
#pragma unroll
    for (int nt = 0; nt < 8; nt++)
#pragma unroll
        for (int i = 0; i < 4; i++) o[nt][i] = 0.f;

    const int r0g = q0 + row_w + gID;           // this thread's global rows
    const int r1g = r0g + 8;
    const size_t wrow0 = ((size_t)(b * Hh + h) * Tt + r0g) * (size_t)Tt;
    const size_t wrow1 = wrow0 + 8 * (size_t)Tt;

    const int nkt = 2 * qt + 2;
    for (int kt = 0; kt < nkt; kt++) {
        const int j0 = kt * 64;
        __syncthreads();   // prior PV-mma reads done before K/V overwrite
        for (int idx = tid; idx < 1024; idx += 256) {
            int j = idx >> 4, dc = (idx & 15) << 2;
            float4 kv = *(const float4*)(Kg + (size_t)(j0 + j) * C3 + dc);
            float4 vv = *(const float4*)(Vg + (size_t)(j0 + j) * C3 + dc);
            unsigned* kp = Ks + j * SPAD + dc;
            unsigned* vp = Vs + j * SPAD + dc;
            kp[0] = f2tf(kv.x); kp[1] = f2tf(kv.y); kp[2] = f2tf(kv.z); kp[3] = f2tf(kv.w);
            vp[0] = f2tf(vv.x); vp[1] = f2tf(vv.y); vp[2] = f2tf(vv.z); vp[3] = f2tf(vv.w);
        }
        __syncthreads();

        // S = Q K^T : warp rows row_w..+15, cols 0..63
        float s[8][4];
#pragma unroll
        for (int nt = 0; nt < 8; nt++)
#pragma unroll
            for (int i = 0; i < 4; i++) s[nt][i] = 0.f;
#pragma unroll
        for (int ks = 0; ks < 8; ks++) {
            unsigned a0 = Qs[(row_w + gID) * SPAD + ks * 8 + tig];
            unsigned a1 = Qs[(row_w + gID + 8) * SPAD + ks * 8 + tig];
            unsigned a2 = Qs[(row_w + gID) * SPAD + ks * 8 + tig + 4];
            unsigned a3 = Qs[(row_w + gID + 8) * SPAD + ks * 8 + tig + 4];
#pragma unroll
            for (int nt = 0; nt < 8; nt++) {
                unsigned b0 = Ks[(nt * 8 + gID) * SPAD + ks * 8 + tig];
                unsigned b1 = Ks[(nt * 8 + gID) * SPAD + ks * 8 + tig + 4];
                MMA_TF32(s[nt], a0, a1, a2, a3, b0, b1);
            }
        }

        // causal mask (only diagonal-band tiles)
        if (kt >= 2 * qt) {
#pragma unroll
            for (int nt = 0; nt < 8; nt++) {
                int c = j0 + nt * 8 + 2 * tig;
                if (c     > r0g) s[nt][0] = -1e30f;
                if (c + 1 > r0g) s[nt][1] = -1e30f;
                if (c     > r1g) s[nt][2] = -1e30f;
                if (c + 1 > r1g) s[nt][3] = -1e30f;
            }
        }

        // stream raw scores
        if (write_attn) {
#pragma unroll
            for (int nt = 0; nt < 8; nt++) {
                int c = j0 + nt * 8 + 2 * tig;
                float2 v0 = {s[nt][0], s[nt][1]};
                float2 v1 = {s[nt][2], s[nt][3]};
                *(float2*)(attn_w + wrow0 + c) = v0;
                *(float2*)(attn_w + wrow1 + c) = v1;
            }
        }

        // online softmax (quad-shuffle row reductions)
        float tm0 = -1e30f, tm1 = -1e30f;
#pragma unroll
        for (int nt = 0; nt < 8; nt++) {
            tm0 = fmaxf(tm0, fmaxf(s[nt][0], s[nt][1]));
            tm1 = fmaxf(tm1, fmaxf(s[nt][2], s[nt][3]));
        }
        tm0 = fmaxf(tm0, __shfl_xor_sync(0xffffffffu, tm0, 1));
        tm0 = fmaxf(tm0, __shfl_xor_sync(0xffffffffu, tm0, 2));
        tm1 = fmaxf(tm1, __shfl_xor_sync(0xffffffffu, tm1, 1));
        tm1 = fmaxf(tm1, __shfl_xor_sync(0xffffffffu, tm1, 2));

        float mn0 = fmaxf(m0, tm0), mn1 = fmaxf(m1, tm1);
        float f0 = __expf(m0 - mn0), f1 = __expf(m1 - mn1);
        float rs0 = 0.f, rs1 = 0.f;
#pragma unroll
        for (int nt = 0; nt < 8; nt++) {
            s[nt][0] = __expf(s[nt][0] - mn0);
            s[nt][1] = __expf(s[nt][1] - mn0);
            s[nt][2] = __expf(s[nt][2] - mn1);
            s[nt][3] = __expf(s[nt][3] - mn1);
            rs0 += s[nt][0] + s[nt][1];
            rs1 += s[nt][2] + s[nt][3];
        }
        rs0 += __shfl_xor_sync(0xffffffffu, rs0, 1);
        rs0 += __shfl_xor_sync(0xffffffffu, rs0, 2);
        rs1 += __shfl_xor_sync(0xffffffffu, rs1, 1);
        rs1 += __shfl_xor_sync(0xffffffffu, rs1, 2);
        l0 = l0 * f0 + rs0;  m0 = mn0;
        l1 = l1 * f1 + rs1;  m1 = mn1;
#pragma unroll
        for (int nt = 0; nt < 8; nt++) {
            o[nt][0] *= f0; o[nt][1] *= f0;
            o[nt][2] *= f1; o[nt][3] *= f1;
        }

        // P -> smem (tf32), uint2 stores
#pragma unroll
        for (int nt = 0; nt < 8; nt++) {
            uint2 p0 = {f2tf(s[nt][0]), f2tf(s[nt][1])};
            uint2 p1 = {f2tf(s[nt][2]), f2tf(s[nt][3])};
            *(uint2*)&Ps[(row_w + gID) * SPAD + nt * 8 + 2 * tig] = p0;
            *(uint2*)&Ps[(row_w + gID + 8) * SPAD + nt * 8 + 2 * tig] = p1;
        }
        __syncthreads();

        // O += P V
#pragma unroll
        for (int ks = 0; ks < 8; ks++) {
            unsigned a0 = Ps[(row_w + gID) * SPAD + ks * 8 + tig];
            unsigned a1 = Ps[(row_w + gID + 8) * SPAD + ks * 8 + tig];
            unsigned a2 = Ps[(row_w + gID) * SPAD + ks * 8 + tig + 4];
            unsigned a3 = Ps[(row_w + gID + 8) * SPAD + ks * 8 + tig + 4];
#pragma unroll
            for (int nt = 0; nt < 8; nt++) {
                unsigned b0 = Vs[(ks * 8 + tig) * SPAD + nt * 8 + gID];
                unsigned b1 = Vs[(ks * 8 + tig + 4) * SPAD + nt * 8 + gID];
                MMA_TF32(o[nt], a0, a1, a2, a3, b0, b1);
            }
        }
    }

    // epilogue
    float invl0 = 1.f / l0, invl1 = 1.f / l1;
    float* op0 = att_out + ((size_t)b * Tt + r0g) * Cc + h * Dd;
    float* op1 = att_out + ((size_t)b * Tt + r1g) * Cc + h * Dd;
#pragma unroll
    for (int nt = 0; nt < 8; nt++) {
        int c = nt * 8 + 2 * tig;
        float2 v0 = {o[nt][0] * invl0, o[nt][1] * invl0};
        float2 v1 = {o[nt][2] * invl1, o[nt][3] * invl1};
        *(float2*)(op0 + c) = v0;
        *(float2*)(op1 + c) = v1;
    }
    if (tig == 0) {
        size_t row = (size_t)(b * Hh + h) * Tt + r0g;
        ml[row * 2] = m0;  ml[row * 2 + 1] = l0;
        ml[(row + 8) * 2] = m1;  ml[(row + 8) * 2 + 1] = l1;
    }
}

// ---------------------------------------------------------------------------
// Normalization: read only causal region; zeros elsewhere.
// ---------------------------------------------------------------------------
__global__ __launch_bounds__(256) void attn_norm_kernel(
    float* __restrict__ attn_w, const float* __restrict__ ml)
{
    const int row = blockIdx.x;
    const int q = row & (Tt - 1);
    const float mrow = ml[(size_t)row * 2];
    const float invl = 1.f / ml[(size_t)row * 2 + 1];
    float* base = attn_w + (size_t)row * Tt;

    for (int c0 = threadIdx.x * 4; c0 < Tt; c0 += 256 * 4) {
        if (c0 > q) {
            float4 z = {0.f, 0.f, 0.f, 0.f};
            *(float4*)(base + c0) = z;
        } else {
            float4 s = *(const float4*)(base + c0);
            float4 w;
            w.x = (c0 + 0 > q) ? 0.f : __expf(s.x - mrow) * invl;
            w.y = (c0 + 1 > q) ? 0.f : __expf(s.y - mrow) * invl;
            w.z = (c0 + 2 > q) ? 0.f : __expf(s.z - mrow) * invl;
            w.w = (c0 + 3 > q) ? 0.f : __expf(s.w - mrow) * invl;
            *(float4*)(base + c0) = w;
        }
    }
}

// ---------------------------------------------------------------------------
extern "C" void kernel_launch(void* const* d_in, const int* in_sizes, int n_in,
                              void* d_out, int out_size)
{
    const float* x     = (const float*)d_in[0];
    const float* w_qkv = (const float*)d_in[1];
    const float* b_qkv = (const float*)d_in[2];
    const float* w_o   = (const float*)d_in[3];
    const float* b_o   = (const float*)d_in[4];
    float* out = (float*)d_out;

    float *qkv_ptr, *att_ptr, *ml_ptr;
    cudaGetSymbolAddress((void**)&qkv_ptr, g_qkv);
    cudaGetSymbolAddress((void**)&att_ptr, g_att);
    cudaGetSymbolAddress((void**)&ml_ptr, g_ml);

    const size_t o_elems    = (size_t)Bb * Tt * Cc;
    const size_t attn_elems = (size_t)Bb * Hh * Tt * (size_t)Tt;
    int write_attn = ((size_t)out_size >= o_elems + attn_elems) ? 1 : 0;
    float* attn_w_ptr = write_attn ? (out + o_elems) : nullptr;

    const int attn_smem = (128 + 64 + 64 + 128) * SPAD * sizeof(unsigned); // 104448
    cudaFuncSetAttribute(attn_tc_kernel,
                         cudaFuncAttributeMaxDynamicSharedMemorySize, attn_smem);

    // 1) QKV projection (tf32 tensor cores)
    {
        dim3 grid(C3 / 128, BT / 128);
        gemm_tc_kernel<<<grid, 256>>>(x, w_qkv, b_qkv, qkv_ptr, BT, C3, Cc);
    }
    // 2) causal attention (tensor cores; raw scores + m,l + attn_v)
    {
        dim3 grid(Tt / 128, Hh, Bb);
        attn_tc_kernel<<<grid, 256, attn_smem>>>(qkv_ptr, attn_w_ptr, att_ptr,
                                                 ml_ptr, write_attn);
    }
    // 3) normalize attn_w
    if (write_attn) {
        attn_norm_kernel<<<Bb * Hh * Tt, 256>>>(attn_w_ptr, ml_ptr);
    }
    // 4) output projection (tf32 tensor cores)
    {
        dim3 grid(Cc / 128, BT / 128);
        gemm_tc_kernel<<<grid, 256>>>(att_ptr, w_o, b_o, out, BT, Cc, Cc);
    }
}